// round 6
// baseline (speedup 1.0000x reference)
#include <cuda_runtime.h>
#include <cuda_bf16.h>

#define NCAM 16

// ---------- f32x2 packed-math helpers (sm_103a) ----------
__device__ __forceinline__ unsigned long long pk2(float a, float b) {
    unsigned long long r;
    asm("mov.b64 %0, {%1, %2};" : "=l"(r) : "f"(a), "f"(b));
    return r;
}
__device__ __forceinline__ void upk2(unsigned long long v, float& a, float& b) {
    asm("mov.b64 {%0, %1}, %2;" : "=f"(a), "=f"(b) : "l"(v));
}
__device__ __forceinline__ unsigned long long fma2(unsigned long long a,
                                                   unsigned long long b,
                                                   unsigned long long c) {
    unsigned long long d;
    asm("fma.rn.f32x2 %0, %1, %2, %3;" : "=l"(d) : "l"(a), "l"(b), "l"(c));
    return d;
}
__device__ __forceinline__ unsigned long long mul2(unsigned long long a,
                                                   unsigned long long b) {
    unsigned long long d;
    asm("mul.rn.f32x2 %0, %1, %2;" : "=l"(d) : "l"(a), "l"(b));
    return d;
}
__device__ __forceinline__ float frcp(float x) {
    float r;
    asm("rcp.approx.f32 %0, %1;" : "=f"(r) : "f"(x));
    return r;
}

// Shared param layout per camera: 16 duplicated (v,v) pairs (128 B):
//   k 0..8 : r00 r01 r02 r10 r11 r12 r20 r21 r22
//   k 9..11: t0 t1 t2    k 12,13: f0 f1    k 14,15: c0 c1

__global__ __launch_bounds__(256, 4)
void Projection_19713899889207_kernel(
    const float* __restrict__ pt3d,   // (3, Np) SoA
    const float* __restrict__ R,      // (NC, 3, 3)
    const float* __restrict__ t,      // (NC, 3)
    const float* __restrict__ f,      // (NC, 2)
    const float* __restrict__ c,      // (NC, 2)
    float* __restrict__ out,          // (NC*Np, 2)
    int np)
{
    __shared__ __align__(16) float sp[NCAM * 32];

    const int tid = threadIdx.x;
    #pragma unroll
    for (int s = tid; s < NCAM * 32; s += 256) {
        const int cam = s >> 5;
        const int k   = (s & 31) >> 1;
        float v;
        if (k < 9)       v = R[cam * 9 + k];
        else if (k < 12) v = t[cam * 3 + (k - 9)];
        else if (k < 14) v = f[cam * 2 + (k - 12)];
        else             v = c[cam * 2 + (k - 14)];
        sp[s] = v;
    }
    __syncthreads();

    const int i = blockIdx.x * blockDim.x + tid;   // index of a QUAD of points
    const int np4 = np >> 2;
    if (i >= np4) return;

    // 4 consecutive points per thread: one LDG.128 per SoA plane.
    // Each ulonglong2 = two f32x2 operands: (p0,p1) and (p2,p3).
    const ulonglong2 x =
        __ldg(reinterpret_cast<const ulonglong2*>(pt3d) + i);
    const ulonglong2 y =
        __ldg(reinterpret_cast<const ulonglong2*>(pt3d + (size_t)np) + i);
    const ulonglong2 z =
        __ldg(reinterpret_cast<const ulonglong2*>(pt3d + 2 * (size_t)np) + i);

    // Incremental output pointer: row block for cam0 starts at point 4i.
    // Per-camera stride = np points * 2 floats = np/2 float4s.
    float4* o = reinterpret_cast<float4*>(out) + (size_t)i * 2;
    const size_t cam_stride_f4 = (size_t)(np >> 1);

    #pragma unroll 1
    for (int cam = 0; cam < NCAM; ++cam) {
        const ulonglong2* Q = reinterpret_cast<const ulonglong2*>(sp + cam * 32);
        const ulonglong2 q0 = Q[0];  // (r00d, r01d)
        const ulonglong2 q1 = Q[1];  // (r02d, r10d)
        const ulonglong2 q2 = Q[2];  // (r11d, r12d)
        const ulonglong2 q3 = Q[3];  // (r20d, r21d)
        const ulonglong2 q4 = Q[4];  // (r22d, t0d)
        const ulonglong2 q5 = Q[5];  // (t1d,  t2d)
        const ulonglong2 q6 = Q[6];  // (f0d,  f1d)
        const ulonglong2 q7 = Q[7];  // (c0d,  c1d)

        // pair A = points (0,1), pair B = points (2,3)
        const unsigned long long XA =
            fma2(q0.x, x.x, fma2(q0.y, y.x, fma2(q1.x, z.x, q4.y)));
        const unsigned long long XB =
            fma2(q0.x, x.y, fma2(q0.y, y.y, fma2(q1.x, z.y, q4.y)));
        const unsigned long long YA =
            fma2(q1.y, x.x, fma2(q2.x, y.x, fma2(q2.y, z.x, q5.x)));
        const unsigned long long YB =
            fma2(q1.y, x.y, fma2(q2.x, y.y, fma2(q2.y, z.y, q5.x)));
        const unsigned long long ZA =
            fma2(q3.x, x.x, fma2(q3.y, y.x, fma2(q4.x, z.x, q5.y)));
        const unsigned long long ZB =
            fma2(q3.x, x.y, fma2(q3.y, y.y, fma2(q4.x, z.y, q5.y)));

        float za0, za1, zb0, zb1;
        upk2(ZA, za0, za1);
        upk2(ZB, zb0, zb1);
        const unsigned long long IZA = pk2(frcp(za0), frcp(za1));
        const unsigned long long IZB = pk2(frcp(zb0), frcp(zb1));

        const unsigned long long UA = fma2(mul2(XA, IZA), q6.x, q7.x);
        const unsigned long long VA = fma2(mul2(YA, IZA), q6.y, q7.y);
        const unsigned long long UB = fma2(mul2(XB, IZB), q6.x, q7.x);
        const unsigned long long VB = fma2(mul2(YB, IZB), q6.y, q7.y);

        float ua0, ua1, va0, va1, ub0, ub1, vb0, vb1;
        upk2(UA, ua0, ua1);
        upk2(VA, va0, va1);
        upk2(UB, ub0, ub1);
        upk2(VB, vb0, vb1);

        // 2 contiguous float4 stores: (u0,v0,u1,v1), (u2,v2,u3,v3)
        __stcs(o,     make_float4(ua0, va0, ua1, va1));
        __stcs(o + 1, make_float4(ub0, vb0, ub1, vb1));
        o += cam_stride_f4;
    }
}

extern "C" void kernel_launch(void* const* d_in, const int* in_sizes, int n_in,
                              void* d_out, int out_size)
{
    // metadata order: pt3d (3,Np) f32, R (16,3,3) f32, t (16,3) f32,
    //                 f (16,2) f32, c (16,2) f32, mask (16,Np) i32 (unused)
    const float* pt3d = (const float*)d_in[0];
    const float* R    = (const float*)d_in[1];
    const float* t    = (const float*)d_in[2];
    const float* f    = (const float*)d_in[3];
    const float* c    = (const float*)d_in[4];
    float* out        = (float*)d_out;

    const int np  = in_sizes[0] / 3;        // 2,000,000
    const int np4 = np / 4;
    const int threads = 256;
    const int blocks  = (np4 + threads - 1) / threads;

    Projection_19713899889207_kernel<<<blocks, threads>>>(pt3d, R, t, f, c, out, np);
}